// round 1
// baseline (speedup 1.0000x reference)
#include <cuda_runtime.h>
#include <math.h>

// Scratch for t[b,s]  (B=128, S=4096)
__device__ float g_t[128 * 4096];

// ---------------------------------------------------------------------------
// Kernel 1: per-token transform  t[b,s] = w2·relu(w1·x + b1) + b2
// One warp per row (128 floats = 32 lanes × float4), 4 rows per iteration
// to front-batch the LDG.128s (MLP). Pure HBM stream: 268 MB in, 2 MB out.
// ---------------------------------------------------------------------------
__global__ void k_transform(const float* __restrict__ x,
                            const float* __restrict__ w1,
                            const float* __restrict__ b1,
                            const float* __restrict__ w2,
                            const float* __restrict__ b2,
                            int rows)
{
    const int lane   = threadIdx.x & 31;
    const int gwarp  = blockIdx.x * (blockDim.x >> 5) + (threadIdx.x >> 5);
    const int nwarps = gridDim.x * (blockDim.x >> 5);

    // Weights: w1 is (2,128). Each lane holds its float4 slice of both rows.
    const float4 a0 = reinterpret_cast<const float4*>(w1)[lane];
    const float4 a1 = reinterpret_cast<const float4*>(w1 + 128)[lane];
    const float bb0 = b1[0], bb1 = b1[1];
    const float c0 = w2[0], c1 = w2[1], cb = b2[0];

    const float4* __restrict__ X = reinterpret_cast<const float4*>(x);

    const int base   = gwarp * 4;
    const int stride = nwarps * 4;

    for (int r = base; r < rows; r += stride) {
        float4 v[4];
        const int nr = min(4, rows - r);
        #pragma unroll
        for (int j = 0; j < 4; ++j)
            if (j < nr) v[j] = X[(size_t)(r + j) * 32 + lane];

        float d0[4], d1[4];
        #pragma unroll
        for (int j = 0; j < 4; ++j) {
            d0[j] = v[j].x * a0.x + v[j].y * a0.y + v[j].z * a0.z + v[j].w * a0.w;
            d1[j] = v[j].x * a1.x + v[j].y * a1.y + v[j].z * a1.z + v[j].w * a1.w;
        }
        #pragma unroll
        for (int off = 16; off; off >>= 1) {
            #pragma unroll
            for (int j = 0; j < 4; ++j) {
                d0[j] += __shfl_xor_sync(0xffffffffu, d0[j], off);
                d1[j] += __shfl_xor_sync(0xffffffffu, d1[j], off);
            }
        }
        if (lane == 0) {
            #pragma unroll
            for (int j = 0; j < 4; ++j) {
                if (j < nr) {
                    float h0 = fmaxf(d0[j] + bb0, 0.0f);
                    float h1 = fmaxf(d1[j] + bb1, 0.0f);
                    g_t[r + j] = c0 * h0 + c1 * h1 + cb;
                }
            }
        }
    }
}

// ---------------------------------------------------------------------------
// Kernel 2: per-batch stats + head + broadcast.
// One block per batch. log|t[s+2]-t[s]| stats in double (single-pass std,
// ddof=1 needs the headroom), then out[b,i,j] = tanh(feat @ w3^T + b3)
// broadcast over i.
// ---------------------------------------------------------------------------
__global__ void k_feature(const float* __restrict__ w3,
                          const float* __restrict__ b3,
                          float* __restrict__ out,
                          int S, int dout)
{
    const int b   = blockIdx.x;
    const int tid = threadIdx.x;
    const int N   = S - 2;                       // DELAY = 2
    const float* __restrict__ tb = g_t + (size_t)b * S;

    double s = 0.0, ss = 0.0;
    for (int i = tid; i < N; i += blockDim.x) {
        float d = fabsf(tb[i + 2] - tb[i]);      // norm over E=1 dim == abs
        float l = logf(d + 1e-6f);
        s  += (double)l;
        ss += (double)l * (double)l;
    }

    // Warp reduce
    #pragma unroll
    for (int off = 16; off; off >>= 1) {
        s  += __shfl_xor_sync(0xffffffffu, s,  off);
        ss += __shfl_xor_sync(0xffffffffu, ss, off);
    }

    __shared__ double sh_s[32], sh_ss[32];
    __shared__ float  sh_stats[2];
    const int wid  = tid >> 5;
    const int lane = tid & 31;
    if (lane == 0) { sh_s[wid] = s; sh_ss[wid] = ss; }
    __syncthreads();

    if (wid == 0) {
        const int nw = blockDim.x >> 5;
        double ts  = (lane < nw) ? sh_s[lane]  : 0.0;
        double tss = (lane < nw) ? sh_ss[lane] : 0.0;
        #pragma unroll
        for (int off = 16; off; off >>= 1) {
            ts  += __shfl_xor_sync(0xffffffffu, ts,  off);
            tss += __shfl_xor_sync(0xffffffffu, tss, off);
        }
        if (lane == 0) {
            double mean = ts / (double)N;
            double var  = (tss - ts * ts / (double)N) / (double)(N - 1);
            if (var < 0.0) var = 0.0;
            sh_stats[0] = (float)mean;
            sh_stats[1] = (float)sqrt(var);
        }
    }
    __syncthreads();

    __shared__ float sh_o[64];
    const float mean = sh_stats[0];
    const float stdv = sh_stats[1];
    if (tid < dout)
        sh_o[tid] = tanhf(mean * w3[2 * tid] + stdv * w3[2 * tid + 1] + b3[tid]);
    __syncthreads();

    float* __restrict__ ob = out + (size_t)b * dout * dout;
    const int total = dout * dout;
    for (int k = tid; k < total; k += blockDim.x)
        ob[k] = sh_o[k % dout];
}

extern "C" void kernel_launch(void* const* d_in, const int* in_sizes, int n_in,
                              void* d_out, int out_size)
{
    const float* x  = (const float*)d_in[0];
    const float* w1 = (const float*)d_in[1];
    const float* b1 = (const float*)d_in[2];
    const float* w2 = (const float*)d_in[3];
    const float* b2 = (const float*)d_in[4];
    const float* w3 = (const float*)d_in[5];
    const float* b3 = (const float*)d_in[6];
    float* out = (float*)d_out;

    const int DOUT = 64;
    const int B    = out_size / (DOUT * DOUT);          // 128
    const int rows = in_sizes[0] / 128;                 // B * S
    const int S    = rows / B;                          // 4096

    // K1: 8 CTAs/SM worth of blocks, 256 threads (8 warps) each.
    k_transform<<<1184, 256>>>(x, w1, b1, w2, b2, rows);

    // K2: one block per batch.
    k_feature<<<B, 512>>>(w3, b3, out, S, DOUT);
}